// round 2
// baseline (speedup 1.0000x reference)
#include <cuda_runtime.h>

// MemN2N on GB300 (sm_103a)
// B=128, M=200, S=20, D=128, V=100000, NC=10000, CL=10, 3 hops.
// Input order (metadata): stories(i64), queries(i64), candidates(i64),
//                         A_tab(f32 V*D), W_tab(f32 V*D), H_w(f32 D*D)
// Output: logits f32 [B, NC]

#define NB   128
#define NM   200
#define NS   20
#define ND   128
#define NCN  10000
#define NCL  10

// scratch (device globals: allocation-free)
__device__ float g_m[NB * NM * ND];   // 13.1 MB memory encodings
__device__ float g_u[NB * ND];        // final query state after hops
__device__ int   g_is64;

// ---------------------------------------------------------------------------
// dtype detection: indices are in [0, 100000). If stored as int64 (LE), the
// odd 32-bit words (high halves) of the first elements are all zero. If int32,
// they are random values — all-zero has probability ~1e-20.
__global__ void k_detect(const int* __restrict__ sw) {
    g_is64 = (sw[1] == 0 && sw[3] == 0 && sw[5] == 0 && sw[7] == 0) ? 1 : 0;
}

__device__ __forceinline__ int load_idx(const int* __restrict__ p, int i, int is64) {
    return is64 ? p[2 * i] : p[i];
}

// ---------------------------------------------------------------------------
// K1: m[b][mm][:] = sum_s A[stories[b][mm][s]]  (padding_idx 0 -> zero row)
// warp per (b,mm) pair; lane loads float4 column chunk -> one LDG.128 per row.
__global__ __launch_bounds__(256) void k_mem(const int* __restrict__ stories,
                                             const float4* __restrict__ A4) {
    int p    = blockIdx.x * 8 + (threadIdx.x >> 5);   // (b*NM + mm), exact: 3200*8=25600
    int lane = threadIdx.x & 31;
    int is64 = g_is64;
    int base = p * NS;
    float4 acc = make_float4(0.f, 0.f, 0.f, 0.f);
#pragma unroll
    for (int s = 0; s < NS; s++) {
        int idx = load_idx(stories, base + s, is64);
        if (idx != 0) {
            float4 v = A4[(size_t)idx * 32 + lane];
            acc.x += v.x; acc.y += v.y; acc.z += v.z; acc.w += v.w;
        }
    }
    reinterpret_cast<float4*>(g_m)[(size_t)p * 32 + lane] = acc;
}

// ---------------------------------------------------------------------------
// K2: one block per b. Loads m[b] (102400B) + H (65536B) into smem, computes
// u0 from queries, runs 3 hops entirely in shared memory, writes g_u.
__global__ __launch_bounds__(256) void k_hops(const int* __restrict__ queries,
                                              const float* __restrict__ A,
                                              const float* __restrict__ Hw) {
    extern __shared__ float sm[];
    float* sm_m    = sm;                       // NM*ND = 25600 floats
    float* sm_H    = sm_m + NM * ND;           // 16384
    float* sm_u    = sm_H + ND * ND;           // 128
    float* sm_dot  = sm_u + ND;                // 200
    float* sm_prob = sm_dot + NM;              // 200
    float* sm_o    = sm_prob + NM;             // 128
    float* sm_hu   = sm_o + ND;                // 128
    float* sm_red  = sm_hu + ND;               // 64

    int b    = blockIdx.x;
    int tid  = threadIdx.x;
    int lane = tid & 31;
    int wid  = tid >> 5;
    int is64 = g_is64;

    // stage m[b] slice into smem (6400 float4)
    const float4* gm4 = reinterpret_cast<const float4*>(g_m) + (size_t)b * NM * 32;
    float4* smm4 = reinterpret_cast<float4*>(sm_m);
    for (int i = tid; i < NM * 32; i += 256) smm4[i] = gm4[i];
    // stage H (4096 float4)
    const float4* H4 = reinterpret_cast<const float4*>(Hw);
    float4* smH4 = reinterpret_cast<float4*>(sm_H);
    for (int i = tid; i < 4096; i += 256) smH4[i] = H4[i];
    // u0 = sum_s A[queries[b][s]]  (thread d per column, coalesced)
    if (tid < ND) {
        float u = 0.f;
        int qb = b * NS;
#pragma unroll
        for (int s = 0; s < NS; s++) {
            int idx = load_idx(queries, qb + s, is64);
            if (idx != 0) u += A[(size_t)idx * ND + tid];
        }
        sm_u[tid] = u;
    }
    __syncthreads();

    for (int hop = 0; hop < 3; hop++) {
        // dotted[mm] = dot(m[mm], u): warp wid handles mm = wid + 8*t
        float4 u4 = reinterpret_cast<float4*>(sm_u)[lane];
#pragma unroll
        for (int t = 0; t < 25; t++) {
            int mm = wid + 8 * t;
            float4 mv = reinterpret_cast<float4*>(sm_m)[mm * 32 + lane];
            float d = mv.x * u4.x + mv.y * u4.y + mv.z * u4.z + mv.w * u4.w;
#pragma unroll
            for (int o = 16; o; o >>= 1) d += __shfl_xor_sync(0xffffffffu, d, o);
            if (lane == 0) sm_dot[mm] = d;
        }
        __syncthreads();

        // softmax over 200 (max-subtract, sum folded as 1/sum later)
        float v = (tid < NM) ? sm_dot[tid] : -1e30f;
        float r = v;
#pragma unroll
        for (int o = 16; o; o >>= 1) r = fmaxf(r, __shfl_xor_sync(0xffffffffu, r, o));
        if (lane == 0) sm_red[wid] = r;
        __syncthreads();
        if (tid < 32) {
            float rr = (tid < 8) ? sm_red[tid] : -1e30f;
#pragma unroll
            for (int o = 4; o; o >>= 1) rr = fmaxf(rr, __shfl_xor_sync(0xffffffffu, rr, o));
            if (tid == 0) sm_red[32] = rr;
        }
        __syncthreads();
        float mx = sm_red[32];
        float e = (tid < NM) ? __expf(v - mx) : 0.f;
        if (tid < NM) sm_prob[tid] = e;
        float s = e;
#pragma unroll
        for (int o = 16; o; o >>= 1) s += __shfl_xor_sync(0xffffffffu, s, o);
        if (lane == 0) sm_red[wid] = s;
        __syncthreads();
        if (tid < 32) {
            float ss = (tid < 8) ? sm_red[tid] : 0.f;
#pragma unroll
            for (int o = 4; o; o >>= 1) ss += __shfl_xor_sync(0xffffffffu, ss, o);
            if (tid == 0) sm_red[33] = ss;
        }
        __syncthreads();
        float inv = 1.0f / sm_red[33];

        // threads [0,128): o[d] = sum_m e_m * m[m][d]
        // threads [128,256): hu[d] = sum_j H[d][(d+j)&127] * u[(d+j)&127] (diag swizzle)
        if (tid < ND) {
            int d = tid;
            float o = 0.f;
#pragma unroll 4
            for (int mm = 0; mm < NM; mm++) o += sm_prob[mm] * sm_m[mm * ND + d];
            sm_o[d] = o;
        } else {
            int d = tid - ND;
            float hu = 0.f;
#pragma unroll 4
            for (int j = 0; j < ND; j++) {
                int dp = (d + j) & (ND - 1);
                hu += sm_H[d * ND + dp] * sm_u[dp];
            }
            sm_hu[d] = hu;
        }
        __syncthreads();
        if (tid < ND) sm_u[tid] = tanhf(sm_hu[tid] + sm_o[tid] * inv);
        __syncthreads();
    }
    if (tid < ND) g_u[b * ND + tid] = sm_u[tid];
}

// ---------------------------------------------------------------------------
// K3: fused candidate encoding + logits GEMM with packed fma.rn.f32x2.
// Block: 64 candidates, 256 threads. Thread tile: 16 b (broadcast LDS) x 2 c.
#define FFMA2(acc, a, b) \
    asm("fma.rn.f32x2 %0, %1, %2, %0;" : "+l"(acc) : "l"(a), "l"(b))

__device__ __forceinline__ float ul_sum(unsigned long long v) {
    float lo, hi;
    asm("mov.b64 {%0,%1}, %2;" : "=f"(lo), "=f"(hi) : "l"(v));
    return lo + hi;
}

__global__ __launch_bounds__(256) void k_logits(const int* __restrict__ cand,
                                                const float4* __restrict__ W4,
                                                float* __restrict__ out) {
    extern __shared__ float sm[];
    float* sm_u  = sm;                 // [128][132] padded
    float* sm_cs = sm + NB * 132;      // [64][132] padded
    int tid  = threadIdx.x;
    int lane = tid & 31;
    int wid  = tid >> 5;
    int is64 = g_is64;

    // stage u with pad-132 stride (LDS.128 quarter-warp conflict-free)
    for (int i = tid; i < NB * 32; i += 256) {
        int b = i >> 5, q = i & 31;
        *reinterpret_cast<float4*>(sm_u + b * 132 + q * 4) =
            reinterpret_cast<const float4*>(g_u)[i];
    }

    // candidate sums: warp wid computes candidates wid*8 .. wid*8+7
    int c0 = blockIdx.x * 64;
#pragma unroll
    for (int j = 0; j < 8; j++) {
        int cl = wid * 8 + j;
        int c  = c0 + cl;
        float4 acc = make_float4(0.f, 0.f, 0.f, 0.f);
        if (c < NCN) {
            int base = c * NCL;
#pragma unroll
            for (int l = 0; l < NCL; l++) {
                int idx = load_idx(cand, base + l, is64);
                if (idx != 0) {
                    float4 v = W4[(size_t)idx * 32 + lane];
                    acc.x += v.x; acc.y += v.y; acc.z += v.z; acc.w += v.w;
                }
            }
        }
        *reinterpret_cast<float4*>(sm_cs + cl * 132 + lane * 4) = acc;
    }
    __syncthreads();

    // GEMM: c = lane + 32*jc (jc 0..1), b = wid + 8*ib (ib 0..15)
    unsigned long long acc[16][2];
#pragma unroll
    for (int ib = 0; ib < 16; ib++) { acc[ib][0] = 0ull; acc[ib][1] = 0ull; }

#pragma unroll 4
    for (int k = 0; k < ND; k += 4) {
        ulonglong2 cs0 = *reinterpret_cast<const ulonglong2*>(sm_cs + lane * 132 + k);
        ulonglong2 cs1 = *reinterpret_cast<const ulonglong2*>(sm_cs + (lane + 32) * 132 + k);
#pragma unroll
        for (int ib = 0; ib < 16; ib++) {
            int b = wid + 8 * ib;
            ulonglong2 uq = *reinterpret_cast<const ulonglong2*>(sm_u + b * 132 + k);
            FFMA2(acc[ib][0], uq.x, cs0.x);
            FFMA2(acc[ib][0], uq.y, cs0.y);
            FFMA2(acc[ib][1], uq.x, cs1.x);
            FFMA2(acc[ib][1], uq.y, cs1.y);
        }
    }

    // coalesced stores along candidate dim
#pragma unroll
    for (int ib = 0; ib < 16; ib++) {
        int b = wid + 8 * ib;
#pragma unroll
        for (int jc = 0; jc < 2; jc++) {
            int c = c0 + lane + 32 * jc;
            if (c < NCN) out[(size_t)b * NCN + c] = ul_sum(acc[ib][jc]);
        }
    }
}

// ---------------------------------------------------------------------------
extern "C" void kernel_launch(void* const* d_in, const int* in_sizes, int n_in,
                              void* d_out, int out_size) {
    const int*    stories = (const int*)d_in[0];
    const int*    queries = (const int*)d_in[1];
    const int*    cand    = (const int*)d_in[2];
    const float*  A_tab   = (const float*)d_in[3];
    const float*  W_tab   = (const float*)d_in[4];
    const float*  H_w     = (const float*)d_in[5];
    float* out = (float*)d_out;

    const int hops_smem   = (NM * ND + ND * ND + ND + NM + NM + ND + ND + 64) * 4; // 171328 B
    const int logits_smem = (NB * 132 + 64 * 132) * 4;                             // 101376 B
    cudaFuncSetAttribute(k_hops,   cudaFuncAttributeMaxDynamicSharedMemorySize, hops_smem);
    cudaFuncSetAttribute(k_logits, cudaFuncAttributeMaxDynamicSharedMemorySize, logits_smem);

    k_detect<<<1, 1>>>(stories);
    k_mem<<<(NB * NM) / 8, 256>>>(stories, (const float4*)A_tab);
    k_hops<<<NB, 256, hops_smem>>>(queries, A_tab, H_w);
    k_logits<<<(NCN + 63) / 64, 256, logits_smem>>>(cand, (const float4*)W_tab, out);
}

// round 3
// speedup vs baseline: 1.1424x; 1.1424x over previous
#include <cuda_runtime.h>

// MemN2N on GB300 (sm_103a)
// B=128, M=200, S=20, D=128, V=100000, NC=10000, CL=10, 3 hops.
// Inputs: stories(i64), queries(i64), candidates(i64),
//         A_tab(f32 V*D), W_tab(f32 V*D), H_w(f32 D*D)
// Output: logits f32 [B, NC]

#define NB   128
#define NM   200
#define NS   20
#define ND   128
#define NCN  10000
#define NCL  10
#define TC   40     // candidates per k_logits block (250*40 == 10000 exactly)

// scratch (device globals: allocation-free)
__device__ float g_m[NB * NM * ND];     // 13.1 MB memory encodings
__device__ float g_cs[NCN * ND];        // 5.12 MB candidate sums
__device__ float g_u[NB * ND];          // query state after hops

__device__ __forceinline__ int detect64(const int* __restrict__ p) {
    // values < 100000: if int64 (LE), high words of first elements are 0.
    return (p[1] == 0 && p[3] == 0 && p[5] == 0 && p[7] == 0) ? 1 : 0;
}
__device__ __forceinline__ int load_idx(const int* __restrict__ p, int i, int is64) {
    return is64 ? p[2 * i] : p[i];
}

// ---------------------------------------------------------------------------
// K1: all embedding gathers. Warp w:
//   w < 25600          -> m[w][:]  = sum_s A[stories[w][s]]
//   w in [25600,35600) -> cs[c][:] = sum_l W[cand[c][l]]   (c = w - 25600)
// grid 4450 * 8 warps = 35600 warps exactly. Lane = float4 column chunk.
__global__ __launch_bounds__(256) void k_gather(const int* __restrict__ stories,
                                                const int* __restrict__ cand,
                                                const float4* __restrict__ A4,
                                                const float4* __restrict__ W4) {
    int w    = blockIdx.x * 8 + (threadIdx.x >> 5);
    int lane = threadIdx.x & 31;
    float4 acc = make_float4(0.f, 0.f, 0.f, 0.f);
    if (w < NB * NM) {
        int is64 = detect64(stories);
        int base = w * NS;
#pragma unroll
        for (int s = 0; s < NS; s++) {
            int idx = load_idx(stories, base + s, is64);
            if (idx != 0) {
                float4 v = A4[(size_t)idx * 32 + lane];
                acc.x += v.x; acc.y += v.y; acc.z += v.z; acc.w += v.w;
            }
        }
        reinterpret_cast<float4*>(g_m)[(size_t)w * 32 + lane] = acc;
    } else {
        int c = w - NB * NM;           // < 10000 by construction
        int is64 = detect64(cand);
        int base = c * NCL;
#pragma unroll
        for (int l = 0; l < NCL; l++) {
            int idx = load_idx(cand, base + l, is64);
            if (idx != 0) {
                float4 v = W4[(size_t)idx * 32 + lane];
                acc.x += v.x; acc.y += v.y; acc.z += v.z; acc.w += v.w;
            }
        }
        reinterpret_cast<float4*>(g_cs)[(size_t)c * 32 + lane] = acc;
    }
}

// ---------------------------------------------------------------------------
// K2: one block per b. m[b] + H staged in smem, 3 hops in shared memory.
__global__ __launch_bounds__(256) void k_hops(const int* __restrict__ queries,
                                              const float* __restrict__ A,
                                              const float* __restrict__ Hw) {
    extern __shared__ float sm[];
    float* sm_m    = sm;                       // NM*ND = 25600 floats
    float* sm_H    = sm_m + NM * ND;           // 16384
    float* sm_u    = sm_H + ND * ND;           // 128
    float* sm_dot  = sm_u + ND;                // 200
    float* sm_prob = sm_dot + NM;              // 200
    float* sm_o    = sm_prob + NM;             // 128
    float* sm_hu   = sm_o + ND;                // 128
    float* sm_red  = sm_hu + ND;               // 64

    int b    = blockIdx.x;
    int tid  = threadIdx.x;
    int lane = tid & 31;
    int wid  = tid >> 5;
    int is64 = detect64(queries);

    const float4* gm4 = reinterpret_cast<const float4*>(g_m) + (size_t)b * NM * 32;
    float4* smm4 = reinterpret_cast<float4*>(sm_m);
    for (int i = tid; i < NM * 32; i += 256) smm4[i] = gm4[i];
    const float4* H4 = reinterpret_cast<const float4*>(Hw);
    float4* smH4 = reinterpret_cast<float4*>(sm_H);
    for (int i = tid; i < 4096; i += 256) smH4[i] = H4[i];
    if (tid < ND) {
        float u = 0.f;
        int qb = b * NS;
#pragma unroll
        for (int s = 0; s < NS; s++) {
            int idx = load_idx(queries, qb + s, is64);
            if (idx != 0) u += A[(size_t)idx * ND + tid];
        }
        sm_u[tid] = u;
    }
    __syncthreads();

    for (int hop = 0; hop < 3; hop++) {
        // attention logits dotted[mm] = dot(m[mm], u)
        float4 u4 = reinterpret_cast<float4*>(sm_u)[lane];
#pragma unroll
        for (int t = 0; t < 25; t++) {
            int mm = wid + 8 * t;
            float4 mv = reinterpret_cast<float4*>(sm_m)[mm * 32 + lane];
            float d = mv.x * u4.x + mv.y * u4.y + mv.z * u4.z + mv.w * u4.w;
#pragma unroll
            for (int o = 16; o; o >>= 1) d += __shfl_xor_sync(0xffffffffu, d, o);
            if (lane == 0) sm_dot[mm] = d;
        }
        __syncthreads();

        // softmax over 200
        float v = (tid < NM) ? sm_dot[tid] : -1e30f;
        float r = v;
#pragma unroll
        for (int o = 16; o; o >>= 1) r = fmaxf(r, __shfl_xor_sync(0xffffffffu, r, o));
        if (lane == 0) sm_red[wid] = r;
        __syncthreads();
        if (tid < 32) {
            float rr = (tid < 8) ? sm_red[tid] : -1e30f;
#pragma unroll
            for (int o = 4; o; o >>= 1) rr = fmaxf(rr, __shfl_xor_sync(0xffffffffu, rr, o));
            if (tid == 0) sm_red[32] = rr;
        }
        __syncthreads();
        float mx = sm_red[32];
        float e = (tid < NM) ? __expf(v - mx) : 0.f;
        if (tid < NM) sm_prob[tid] = e;
        float s = e;
#pragma unroll
        for (int o = 16; o; o >>= 1) s += __shfl_xor_sync(0xffffffffu, s, o);
        if (lane == 0) sm_red[wid] = s;
        __syncthreads();
        if (tid < 32) {
            float ss = (tid < 8) ? sm_red[tid] : 0.f;
#pragma unroll
            for (int o = 4; o; o >>= 1) ss += __shfl_xor_sync(0xffffffffu, ss, o);
            if (tid == 0) sm_red[33] = ss;
        }
        __syncthreads();
        float inv = 1.0f / sm_red[33];

        // threads [0,128): o[d];  threads [128,256): (H u)[d] diag-swizzled
        if (tid < ND) {
            int d = tid;
            float o = 0.f;
#pragma unroll 4
            for (int mm = 0; mm < NM; mm++) o += sm_prob[mm] * sm_m[mm * ND + d];
            sm_o[d] = o;
        } else {
            int d = tid - ND;
            float hu = 0.f;
#pragma unroll 4
            for (int j = 0; j < ND; j++) {
                int dp = (d + j) & (ND - 1);
                hu += sm_H[d * ND + dp] * sm_u[dp];
            }
            sm_hu[d] = hu;
        }
        __syncthreads();
        if (tid < ND) sm_u[tid] = tanhf(sm_hu[tid] + sm_o[tid] * inv);
        __syncthreads();
    }
    if (tid < ND) g_u[b * ND + tid] = sm_u[tid];
}

// ---------------------------------------------------------------------------
// K3: logits GEMM  out[128,10000] = U[128,128] @ CS[10000,128]^T
// grid 250, block 320 (10 warps). Thread tile: 4 b (lane+32*jb) x 4 c (wid*4+jc).
// Per k-chunk (4 k): 4 conflict-free uq LDS.128 + 4 broadcast cs LDS.128 + 32 FFMA2.
// FFMA2 halves accumulate even/odd-k partials (no packing ops needed).
#define FFMA2(acc, a, b) \
    asm("fma.rn.f32x2 %0, %1, %2, %0;" : "+l"(acc) : "l"(a), "l"(b))

__device__ __forceinline__ float ul_sum(unsigned long long v) {
    float lo, hi;
    asm("mov.b64 {%0,%1}, %2;" : "=f"(lo), "=f"(hi) : "l"(v));
    return lo + hi;
}

__global__ __launch_bounds__(320) void k_logits(float* __restrict__ out) {
    extern __shared__ float sm[];
    float* sm_u  = sm;                 // [128][132] padded (row = 528B: per-phase stride 16B mod 128 -> conflict-free LDS.128)
    float* sm_cs = sm + NB * 132;      // [40][132]; reused as [128][41] transpose buffer
    int tid  = threadIdx.x;
    int lane = tid & 31;
    int wid  = tid >> 5;
    int c0   = blockIdx.x * TC;

    // stage u (4096 float4)
    for (int i = tid; i < NB * 32; i += 320) {
        int bb = i >> 5, q = i & 31;
        *reinterpret_cast<float4*>(sm_u + bb * 132 + q * 4) =
            reinterpret_cast<const float4*>(g_u)[i];
    }
    // stage cs tile (1280 float4)
    for (int i = tid; i < TC * 32; i += 320) {
        int cl = i >> 5, q = i & 31;
        *reinterpret_cast<float4*>(sm_cs + cl * 132 + q * 4) =
            reinterpret_cast<const float4*>(g_cs)[(size_t)(c0 + cl) * 32 + q];
    }
    __syncthreads();

    unsigned long long acc[4][4];
#pragma unroll
    for (int jb = 0; jb < 4; jb++)
#pragma unroll
        for (int jc = 0; jc < 4; jc++) acc[jb][jc] = 0ull;

#pragma unroll 8
    for (int k4 = 0; k4 < 32; k4++) {
        ulonglong2 uq[4], cq[4];
#pragma unroll
        for (int jb = 0; jb < 4; jb++)
            uq[jb] = *reinterpret_cast<const ulonglong2*>(sm_u + (lane + 32 * jb) * 132 + k4 * 4);
#pragma unroll
        for (int jc = 0; jc < 4; jc++)
            cq[jc] = *reinterpret_cast<const ulonglong2*>(sm_cs + (wid * 4 + jc) * 132 + k4 * 4);
#pragma unroll
        for (int jb = 0; jb < 4; jb++)
#pragma unroll
            for (int jc = 0; jc < 4; jc++) {
                FFMA2(acc[jb][jc], uq[jb].x, cq[jc].x);
                FFMA2(acc[jb][jc], uq[jb].y, cq[jc].y);
            }
    }

    // transpose through smem for coalesced stores (reuse cs region)
    __syncthreads();
#pragma unroll
    for (int jb = 0; jb < 4; jb++)
#pragma unroll
        for (int jc = 0; jc < 4; jc++)
            sm_cs[(lane + 32 * jb) * 41 + (wid * 4 + jc)] = ul_sum(acc[jb][jc]);
    __syncthreads();
    for (int i = tid; i < NB * TC; i += 320) {
        int bb = i / TC, cl = i % TC;
        out[(size_t)bb * NCN + c0 + cl] = sm_cs[bb * 41 + cl];
    }
}

// ---------------------------------------------------------------------------
extern "C" void kernel_launch(void* const* d_in, const int* in_sizes, int n_in,
                              void* d_out, int out_size) {
    const int*    stories = (const int*)d_in[0];
    const int*    queries = (const int*)d_in[1];
    const int*    cand    = (const int*)d_in[2];
    const float*  A_tab   = (const float*)d_in[3];
    const float*  W_tab   = (const float*)d_in[4];
    const float*  H_w     = (const float*)d_in[5];
    float* out = (float*)d_out;

    const int hops_smem   = (NM * ND + ND * ND + ND + NM + NM + ND + ND + 64) * 4; // 171328 B
    const int logits_smem = (NB * 132 + TC * 132) * 4;                             // 88704 B
    cudaFuncSetAttribute(k_hops,   cudaFuncAttributeMaxDynamicSharedMemorySize, hops_smem);
    cudaFuncSetAttribute(k_logits, cudaFuncAttributeMaxDynamicSharedMemorySize, logits_smem);

    k_gather<<<(NB * NM + NCN) / 8, 256>>>(stories, cand, (const float4*)A_tab,
                                           (const float4*)W_tab);
    k_hops<<<NB, 256, hops_smem>>>(queries, A_tab, H_w);
    k_logits<<<NCN / TC, 320, logits_smem>>>(out);
}

// round 5
// speedup vs baseline: 1.2822x; 1.1224x over previous
#include <cuda_runtime.h>

// MemN2N on GB300 (sm_103a)
// B=128, M=200, S=20, D=128, V=100000, NC=10000, CL=10, 3 hops.
// Inputs: stories(i64), queries(i64), candidates(i64),
//         A_tab(f32 V*D), W_tab(f32 V*D), H_w(f32 D*D)
// Output: logits f32 [B, NC]

#define NB   128
#define NM   200
#define NS   20
#define ND   128
#define NCN  10000
#define NCL  10
#define TC   40     // candidates per k_logits block (250*40 == 10000 exactly)

// scratch (device globals: allocation-free)
__device__ float g_m[NB * NM * ND];     // 13.1 MB memory encodings
__device__ float g_cs[NCN * ND];        // 5.12 MB candidate sums
__device__ float g_u[NB * ND];          // query state after hops

__device__ __forceinline__ int detect64(const int* __restrict__ p) {
    // values < 100000: if int64 (LE), high words of first elements are 0.
    return (p[1] == 0 && p[3] == 0 && p[5] == 0 && p[7] == 0) ? 1 : 0;
}

// ---------------------------------------------------------------------------
// K1: all embedding gathers, restructured for MLP.
//   w < 25600          -> m[w][:]  = sum_s A[stories[w][s]]
//   w in [25600,35600) -> cs[c][:] = sum_l W[cand[c][l]]
// Indices preloaded to registers; gathers issued unconditionally in batches
// (vocab row 0 is valid memory), accumulate predicated on idx!=0.
__global__ __launch_bounds__(256) void k_gather(const int* __restrict__ stories,
                                                const int* __restrict__ cand,
                                                const float4* __restrict__ A4,
                                                const float4* __restrict__ W4) {
    int w    = blockIdx.x * 8 + (threadIdx.x >> 5);
    int lane = threadIdx.x & 31;
    float4 acc = make_float4(0.f, 0.f, 0.f, 0.f);
    if (w < NB * NM) {
        int is64 = detect64(stories);
        int idx[NS];
        if (is64) {
            const int* p = stories + (size_t)w * NS * 2;
#pragma unroll
            for (int s = 0; s < NS; s++) idx[s] = p[2 * s];
        } else {
            const int* p = stories + (size_t)w * NS;
#pragma unroll
            for (int s = 0; s < NS; s++) idx[s] = p[s];
        }
#pragma unroll
        for (int c0 = 0; c0 < NS; c0 += 5) {
            float4 v[5];
#pragma unroll
            for (int j = 0; j < 5; j++)
                v[j] = A4[(size_t)idx[c0 + j] * 32 + lane];
#pragma unroll
            for (int j = 0; j < 5; j++)
                if (idx[c0 + j] != 0) {
                    acc.x += v[j].x; acc.y += v[j].y;
                    acc.z += v[j].z; acc.w += v[j].w;
                }
        }
        reinterpret_cast<float4*>(g_m)[(size_t)w * 32 + lane] = acc;
    } else {
        int c = w - NB * NM;           // < 10000 by construction
        int is64 = detect64(cand);
        int idx[NCL];
        if (is64) {
            const int* p = cand + (size_t)c * NCL * 2;
#pragma unroll
            for (int l = 0; l < NCL; l++) idx[l] = p[2 * l];
        } else {
            const int* p = cand + (size_t)c * NCL;
#pragma unroll
            for (int l = 0; l < NCL; l++) idx[l] = p[l];
        }
#pragma unroll
        for (int c0 = 0; c0 < NCL; c0 += 5) {
            float4 v[5];
#pragma unroll
            for (int j = 0; j < 5; j++)
                v[j] = W4[(size_t)idx[c0 + j] * 32 + lane];
#pragma unroll
            for (int j = 0; j < 5; j++)
                if (idx[c0 + j] != 0) {
                    acc.x += v[j].x; acc.y += v[j].y;
                    acc.z += v[j].z; acc.w += v[j].w;
                }
        }
        reinterpret_cast<float4*>(g_cs)[(size_t)c * 32 + lane] = acc;
    }
}

// ---------------------------------------------------------------------------
// K2: one block (512 threads) per b. m[b] + H staged in smem, 3 hops in smem.
__global__ __launch_bounds__(512) void k_hops(const int* __restrict__ queries,
                                              const float* __restrict__ A,
                                              const float* __restrict__ Hw) {
    extern __shared__ float sm[];
    float* sm_m    = sm;                       // NM*ND = 25600 floats
    float* sm_H    = sm_m + NM * ND;           // 16384
    float* sm_u    = sm_H + ND * ND;           // 128
    float* sm_dot  = sm_u + ND;                // 200
    float* sm_prob = sm_dot + NM;              // 200
    float* sm_o    = sm_prob + NM;             // 256  [2][128] partials
    float* sm_hu   = sm_o + 2 * ND;            // 256  [2][128] partials
    float* sm_red  = sm_hu + 2 * ND;           // 64

    int b    = blockIdx.x;
    int tid  = threadIdx.x;
    int lane = tid & 31;
    int wid  = tid >> 5;     // 0..15

    // stage m[b] (6400 float4) + H (4096 float4)
    const float4* gm4 = reinterpret_cast<const float4*>(g_m) + (size_t)b * NM * 32;
    float4* smm4 = reinterpret_cast<float4*>(sm_m);
    for (int i = tid; i < NM * 32; i += 512) smm4[i] = gm4[i];
    const float4* H4 = reinterpret_cast<const float4*>(Hw);
    float4* smH4 = reinterpret_cast<float4*>(sm_H);
    for (int i = tid; i < 4096; i += 512) smH4[i] = H4[i];

    // u0 = sum_s A[queries[b][s]] : thread d, indices preloaded, batched loads
    if (tid < ND) {
        int is64 = detect64(queries);
        int idx[NS];
        if (is64) {
            const int* p = queries + (size_t)b * NS * 2;
#pragma unroll
            for (int s = 0; s < NS; s++) idx[s] = p[2 * s];
        } else {
            const int* p = queries + (size_t)b * NS;
#pragma unroll
            for (int s = 0; s < NS; s++) idx[s] = p[s];
        }
        float u = 0.f;
#pragma unroll
        for (int c0 = 0; c0 < NS; c0 += 5) {
            float v[5];
#pragma unroll
            for (int j = 0; j < 5; j++) v[j] = A[(size_t)idx[c0 + j] * ND + tid];
#pragma unroll
            for (int j = 0; j < 5; j++) if (idx[c0 + j] != 0) u += v[j];
        }
        sm_u[tid] = u;
    }
    __syncthreads();

    for (int hop = 0; hop < 3; hop++) {
        // dotted[mm] = dot(m[mm], u): warp wid handles mm = wid + 16*t
        float4 u4 = reinterpret_cast<float4*>(sm_u)[lane];
#pragma unroll
        for (int t = 0; t < 13; t++) {
            int mm = wid + 16 * t;
            if (mm < NM) {
                float4 mv = reinterpret_cast<float4*>(sm_m)[mm * 32 + lane];
                float d = mv.x * u4.x + mv.y * u4.y + mv.z * u4.z + mv.w * u4.w;
#pragma unroll
                for (int o = 16; o; o >>= 1) d += __shfl_xor_sync(0xffffffffu, d, o);
                if (lane == 0) sm_dot[mm] = d;
            }
        }
        __syncthreads();

        // softmax over 200 (16-warp block reduce)
        float v = (tid < NM) ? sm_dot[tid] : -1e30f;
        float r = v;
#pragma unroll
        for (int o = 16; o; o >>= 1) r = fmaxf(r, __shfl_xor_sync(0xffffffffu, r, o));
        if (lane == 0) sm_red[wid] = r;
        __syncthreads();
        if (tid < 32) {
            float rr = (tid < 16) ? sm_red[tid] : -1e30f;
#pragma unroll
            for (int o = 8; o; o >>= 1) rr = fmaxf(rr, __shfl_xor_sync(0xffffffffu, rr, o));
            if (tid == 0) sm_red[32] = rr;
        }
        __syncthreads();
        float mx = sm_red[32];
        float e = (tid < NM) ? __expf(v - mx) : 0.f;
        if (tid < NM) sm_prob[tid] = e;
        float s = e;
#pragma unroll
        for (int o = 16; o; o >>= 1) s += __shfl_xor_sync(0xffffffffu, s, o);
        if (lane == 0) sm_red[wid] = s;
        __syncthreads();
        if (tid < 32) {
            float ss = (tid < 16) ? sm_red[tid] : 0.f;
#pragma unroll
            for (int o = 8; o; o >>= 1) ss += __shfl_xor_sync(0xffffffffu, ss, o);
            if (tid == 0) sm_red[33] = ss;
        }
        __syncthreads();
        float inv = 1.0f / sm_red[33];

        // threads [0,256): o-partials, half h covers mm in [100h, 100h+100)
        // threads [256,512): Hu-partials, half h covers j in [64h, 64h+64), diag swizzle
        if (tid < 2 * ND) {
            int d = tid & (ND - 1), h = tid >> 7;
            float o = 0.f;
            int m0 = h * 100;
#pragma unroll 4
            for (int mm = m0; mm < m0 + 100; mm++) o += sm_prob[mm] * sm_m[mm * ND + d];
            sm_o[h * ND + d] = o;
        } else {
            int t2 = tid - 2 * ND;
            int d = t2 & (ND - 1), h = t2 >> 7;
            float hu = 0.f;
            int j0 = h * 64;
#pragma unroll 4
            for (int j = j0; j < j0 + 64; j++) {
                int dp = (d + j) & (ND - 1);
                hu += sm_H[d * ND + dp] * sm_u[dp];
            }
            sm_hu[h * ND + d] = hu;
        }
        __syncthreads();
        if (tid < ND)
            sm_u[tid] = tanhf(sm_hu[tid] + sm_hu[ND + tid]
                              + (sm_o[tid] + sm_o[ND + tid]) * inv);
        __syncthreads();
    }
    if (tid < ND) g_u[b * ND + tid] = sm_u[tid];
}

// ---------------------------------------------------------------------------
// K3: logits GEMM  out[128,10000] = U[128,128] @ CS[10000,128]^T
// grid 250, block 320, 2 CTAs/SM (launch_bounds caps regs at 102).
// Thread tile 4b x 4c; FFMA2 halves hold even/odd-k partials.
#define FFMA2(acc, a, b) \
    asm("fma.rn.f32x2 %0, %1, %2, %0;" : "+l"(acc) : "l"(a), "l"(b))

__device__ __forceinline__ float ul_sum(unsigned long long v) {
    float lo, hi;
    asm("mov.b64 {%0,%1}, %2;" : "=f"(lo), "=f"(hi) : "l"(v));
    return lo + hi;
}

__global__ __launch_bounds__(320, 2) void k_logits(float* __restrict__ out) {
    extern __shared__ float sm[];
    float* sm_u  = sm;                 // [128][132] padded, conflict-free LDS.128
    float* sm_cs = sm + NB * 132;      // [40][132]; reused as [128][41] transpose buf
    int tid  = threadIdx.x;
    int lane = tid & 31;
    int wid  = tid >> 5;
    int c0   = blockIdx.x * TC;

    for (int i = tid; i < NB * 32; i += 320) {
        int bb = i >> 5, q = i & 31;
        *reinterpret_cast<float4*>(sm_u + bb * 132 + q * 4) =
            reinterpret_cast<const float4*>(g_u)[i];
    }
    for (int i = tid; i < TC * 32; i += 320) {
        int cl = i >> 5, q = i & 31;
        *reinterpret_cast<float4*>(sm_cs + cl * 132 + q * 4) =
            reinterpret_cast<const float4*>(g_cs)[(size_t)(c0 + cl) * 32 + q];
    }
    __syncthreads();

    unsigned long long acc[4][4];
#pragma unroll
    for (int jb = 0; jb < 4; jb++)
#pragma unroll
        for (int jc = 0; jc < 4; jc++) acc[jb][jc] = 0ull;

#pragma unroll 8
    for (int k4 = 0; k4 < 32; k4++) {
        ulonglong2 uq[4], cq[4];
#pragma unroll
        for (int jb = 0; jb < 4; jb++)
            uq[jb] = *reinterpret_cast<const ulonglong2*>(sm_u + (lane + 32 * jb) * 132 + k4 * 4);
#pragma unroll
        for (int jc = 0; jc < 4; jc++)
            cq[jc] = *reinterpret_cast<const ulonglong2*>(sm_cs + (wid * 4 + jc) * 132 + k4 * 4);
#pragma unroll
        for (int jb = 0; jb < 4; jb++)
#pragma unroll
            for (int jc = 0; jc < 4; jc++) {
                FFMA2(acc[jb][jc], uq[jb].x, cq[jc].x);
                FFMA2(acc[jb][jc], uq[jb].y, cq[jc].y);
            }
    }

    __syncthreads();
#pragma unroll
    for (int jb = 0; jb < 4; jb++)
#pragma unroll
        for (int jc = 0; jc < 4; jc++)
            sm_cs[(lane + 32 * jb) * 41 + (wid * 4 + jc)] = ul_sum(acc[jb][jc]);
    __syncthreads();
    for (int i = tid; i < NB * TC; i += 320) {
        int bb = i / TC, cl = i % TC;
        out[(size_t)bb * NCN + c0 + cl] = sm_cs[bb * 41 + cl];
    }
}

// ---------------------------------------------------------------------------
extern "C" void kernel_launch(void* const* d_in, const int* in_sizes, int n_in,
                              void* d_out, int out_size) {
    const int*    stories = (const int*)d_in[0];
    const int*    queries = (const int*)d_in[1];
    const int*    cand    = (const int*)d_in[2];
    const float*  A_tab   = (const float*)d_in[3];
    const float*  W_tab   = (const float*)d_in[4];
    const float*  H_w     = (const float*)d_in[5];
    float* out = (float*)d_out;

    const int hops_smem   = (NM * ND + ND * ND + ND + NM + NM + 2 * ND + 2 * ND + 64) * 4; // 172352 B
    const int logits_smem = (NB * 132 + TC * 132) * 4;                                     // 88704 B
    cudaFuncSetAttribute(k_hops,   cudaFuncAttributeMaxDynamicSharedMemorySize, hops_smem);
    cudaFuncSetAttribute(k_logits, cudaFuncAttributeMaxDynamicSharedMemorySize, logits_smem);

    k_gather<<<(NB * NM + NCN) / 8, 256>>>(stories, cand, (const float4*)A_tab,
                                           (const float4*)W_tab);
    k_hops<<<NB, 512, hops_smem>>>(queries, A_tab, H_w);
    k_logits<<<NCN / TC, 320, logits_smem>>>(out);
}